// round 10
// baseline (speedup 1.0000x reference)
#include <cuda_runtime.h>
#include <math.h>

// Problem constants (fixed by reference)
#define B_   8
#define T_   4096
#define D_   64
#define R_   64
#define BT_  (B_ * T_)           // 32768 tokens
#define STRENGTH 0.1f
#define PHI_SCALE 0.17677669529663689f   // sqrt(2/64)
#define NKBLK 1024                // producer blocks, 32 tokens each

// Scratch (static device globals — allocation-free)
__device__ float g_phi[BT_ * R_];          // 8 MB
__device__ float g_part[NKBLK * R_];       // per-producer-block phi_sum partials
__device__ float g_phisum[B_ * R_];        // 2 KB
__device__ int   g_applied[BT_];           // 1 = diagonal fused in main kernel
__device__ unsigned g_count;               // producer completion counter
__device__ int g_flag;                     // phisum-ready flag

typedef unsigned long long u64;

// ---- f32x2 packed helpers (FFMA2 — only reachable via PTX) -----------------
__device__ __forceinline__ u64 pack2(float lo, float hi) {
    u64 v;
    asm("mov.b64 %0, {%1, %2};" : "=l"(v)
        : "r"(__float_as_uint(lo)), "r"(__float_as_uint(hi)));
    return v;
}
__device__ __forceinline__ u64 packdup(float x) {
    u64 v; unsigned u = __float_as_uint(x);
    asm("mov.b64 %0, {%1, %1};" : "=l"(v) : "r"(u));
    return v;
}
__device__ __forceinline__ void unpack2(u64 v, float& lo, float& hi) {
    unsigned a, b;
    asm("mov.b64 {%0, %1}, %2;" : "=r"(a), "=r"(b) : "l"(v));
    lo = __uint_as_float(a); hi = __uint_as_float(b);
}
__device__ __forceinline__ u64 ffma2(u64 a, u64 b, u64 c) {
    u64 d;
    asm("fma.rn.f32x2 %0, %1, %2, %3;" : "=l"(d) : "l"(a), "l"(b), "l"(c));
    return d;
}
__device__ __forceinline__ int ld_acquire(const int* p) {
    int v;
    asm volatile("ld.global.acquire.gpu.b32 %0, [%1];" : "=r"(v) : "l"(p) : "memory");
    return v;
}

// ---------------------------------------------------------------------------
// K0: reset counter/flag (graph replays reuse the globals)
// ---------------------------------------------------------------------------
__global__ void k0_reset() { g_count = 0; g_flag = 0; }

// ---------------------------------------------------------------------------
// Fused kernel. grid = 2048 x 256 threads. Roles interleaved by bid parity so
// every wave contains both producers (phi/mass) and copiers (G streaming).
// NO block ever waits on another: copiers that see the flag unset copy G
// verbatim, mark g_applied[tok]=0, and retire; k_fixup patches them later.
// ---------------------------------------------------------------------------
__global__ __launch_bounds__(256, 5)
void k_fused(const float4* __restrict__ G4, float4* __restrict__ out4,
             const float* __restrict__ coords,
             const float* __restrict__ w1, const float* __restrict__ b1,
             const float* __restrict__ w2, const float* __restrict__ b2,
             const float* __restrict__ W,  const float* __restrict__ b)
{
    __shared__ float2 Wsh2[D_ * 32];   // 16KB
    __shared__ float2 Hsh2[D_ * 32];   // 16KB
    __shared__ float  csh[8][4][D_];   // 8KB
    __shared__ float  psum[8][R_];     // 2KB
    __shared__ float  gsh;
    __shared__ int    ish;

    const int bid  = blockIdx.x;
    const int tid  = threadIdx.x;
    const int wid  = tid >> 5;
    const int lane = tid & 31;

    if ((bid & 1) == 0) {
        // ================= PRODUCER: phi + mass + phisum partial ===========
        const int kblk = bid >> 1;          // 0..1023
        const int tokBase = kblk * 32;

        for (int i = tid; i < D_ * 32; i += 256) {
            const int d = i >> 5, l = i & 31;
            Wsh2[i] = make_float2(W[d * R_ + l], W[d * R_ + l + 32]);
            Hsh2[i] = make_float2(w1[l * D_ + d], w1[(l + 32) * D_ + d]);
        }
        {
            const float4* src = (const float4*)(coords + (size_t)tokBase * D_);
            float4* dstc = (float4*)&csh[0][0][0];
            #pragma unroll
            for (int g = 0; g < 2; ++g) dstc[tid + g * 256] = src[tid + g * 256];
        }
        const float bv_lo = b[lane],  bv_hi = b[lane + 32];
        const float b1_lo = b1[lane], b1_hi = b1[lane + 32];
        const float w2_lo = w2[lane], w2_hi = w2[lane + 32];
        const float b2v   = b2[0];
        __syncthreads();

        u64 accA[4], accH[4];
        {
            const u64 a0 = pack2(bv_lo, bv_hi);
            const u64 h0 = pack2(b1_lo, b1_hi);
            #pragma unroll
            for (int t = 0; t < 4; ++t) { accA[t] = a0; accH[t] = h0; }
        }

        #pragma unroll 1
        for (int dd = 0; dd < 16; ++dd) {
            float4 c4[4];
            #pragma unroll
            for (int t = 0; t < 4; ++t)
                c4[t] = *(const float4*)&csh[wid][t][dd * 4];   // broadcast
            #pragma unroll
            for (int k4 = 0; k4 < 4; ++k4) {
                const int d = dd * 4 + k4;
                const u64 wv = *(const u64*)&Wsh2[d * 32 + lane];
                const u64 hv = *(const u64*)&Hsh2[d * 32 + lane];
                #pragma unroll
                for (int t = 0; t < 4; ++t) {
                    const float c = (k4 == 0) ? c4[t].x : (k4 == 1) ? c4[t].y
                                  : (k4 == 2) ? c4[t].z : c4[t].w;
                    const u64 cc = packdup(c);
                    accA[t] = ffma2(cc, wv, accA[t]);
                    accH[t] = ffma2(cc, hv, accH[t]);
                }
            }
        }

        float ps_lo = 0.0f, ps_hi = 0.0f;
        const int gtok0 = tokBase + wid * 4;
        #pragma unroll 1
        for (int t = 0; t < 4; ++t) {
            float alo, ahi, hlo, hhi;
            unpack2(accA[t], alo, ahi);
            unpack2(accH[t], hlo, hhi);
            const float phi_lo = PHI_SCALE * cosf(alo);
            const float phi_hi = PHI_SCALE * cosf(ahi);
            const size_t po = (size_t)(gtok0 + t) * R_;
            g_phi[po + lane]      = phi_lo;
            g_phi[po + lane + 32] = phi_hi;

            float mp = fmaxf(hlo, 0.0f) * w2_lo + fmaxf(hhi, 0.0f) * w2_hi;
            #pragma unroll
            for (int off = 16; off > 0; off >>= 1)
                mp += __shfl_xor_sync(0xffffffffu, mp, off);
            const float x = mp + b2v;
            const float mass = fmaxf(x, 0.0f) + log1pf(expf(-fabsf(x)));
            ps_lo = fmaf(phi_lo, mass, ps_lo);
            ps_hi = fmaf(phi_hi, mass, ps_hi);
        }

        psum[wid][lane]      = ps_lo;
        psum[wid][lane + 32] = ps_hi;
        __syncthreads();
        if (tid < 64) {
            float s = 0.0f;
            #pragma unroll
            for (int w = 0; w < 8; ++w) s += psum[w][tid];
            g_part[kblk * R_ + tid] = s;
        }
        __syncthreads();
        __threadfence();                       // phi + partial visible device-wide
        if (tid == 0)
            ish = (atomicAdd(&g_count, 1u) == NKBLK - 1u) ? 1 : 0;
        __syncthreads();

        if (ish) {
            // Last producer: reduce 128 chunk-partials per (batch, r), set flag
            for (int p = tid; p < B_ * R_; p += 256) {
                const int batch = p >> 6, r = p & 63;
                const float* base = g_part + (size_t)(batch * 128) * R_ + r;
                float s = 0.0f;
                #pragma unroll 8
                for (int c = 0; c < 128; ++c) s += base[(size_t)c * R_];
                g_phisum[p] = s;
            }
            __syncthreads();
            __threadfence();
            if (tid == 0) atomicExch(&g_flag, 1);   // release
        }
    } else {
        // ================= COPIER: stream G -> out, diag fused when ready ==
        const int cblk = bid >> 1;          // 0..1023
        const int tok0 = cblk * 32;

        #pragma unroll 1
        for (int t = 0; t < 32; ++t) {
            const int tok = tok0 + t;
            const float4* src = G4   + (size_t)tok * 1024;
            float4*       dst = out4 + (size_t)tok * 1024;

            // start the tile's loads immediately (independent of flag)
            float4 v[4];
            #pragma unroll
            for (int i = 0; i < 4; ++i)
                v[i] = __ldcs(&src[tid + i * 256]);

            if (tid == 0) ish = ld_acquire(&g_flag);
            __syncthreads();
            const bool fused = (ish != 0);
            if (fused && tid < 32) {
                const int batch = tok >> 12;
                const float* ph = g_phi    + (size_t)tok * R_;
                const float* ps = g_phisum + batch * R_;
                float s = ph[lane] * ps[lane] + ph[lane + 32] * ps[lane + 32];
                #pragma unroll
                for (int off = 16; off > 0; off >>= 1)
                    s += __shfl_down_sync(0xffffffffu, s, off);
                if (lane == 0) gsh = STRENGTH * s;
            }
            __syncthreads();
            const float g = fused ? gsh : 0.0f;   // +0.0f is exact
            if (tid == 0) g_applied[tok] = fused ? 1 : 0;

            #pragma unroll
            for (int i = 0; i < 4; ++i) {
                const int idx = tid + i * 256;
                const int lin = idx << 2;
                float4 x = v[i];
                if (((lin    ) >> 6) == ((lin    ) & 63)) x.x += g;
                if (((lin + 1) >> 6) == ((lin + 1) & 63)) x.y += g;
                if (((lin + 2) >> 6) == ((lin + 2) & 63)) x.z += g;
                if (((lin + 3) >> 6) == ((lin + 3) & 63)) x.w += g;
                __stcs(&dst[idx], x);
            }
            // NO waiting, NO spin: block retires after its 32 tiles.
        }
    }
}

// ---------------------------------------------------------------------------
// K-fixup: for tiles whose diagonal was NOT fused, add 0.1*grav to the diag.
// Runs after k_fused (kernel boundary = full visibility/ordering).
// Warp per token: 8 tokens per 256-thread block, grid 4096.
// Bit-identical to the fused path: same single fp32 add onto the same value.
// ---------------------------------------------------------------------------
__global__ __launch_bounds__(256)
void k_fixup(float* __restrict__ out)
{
    const int wid  = threadIdx.x >> 5;
    const int lane = threadIdx.x & 31;
    const int tok  = blockIdx.x * 8 + wid;

    if (g_applied[tok]) return;             // warp-uniform

    const int batch = tok >> 12;
    const float* ph = g_phi    + (size_t)tok * R_;
    const float* ps = g_phisum + batch * R_;
    float s = ph[lane] * ps[lane] + ph[lane + 32] * ps[lane + 32];
    #pragma unroll
    for (int off = 16; off > 0; off >>= 1)
        s += __shfl_xor_sync(0xffffffffu, s, off);
    const float g = STRENGTH * s;

    float* o = out + (size_t)tok * 4096;
    o[lane * 65]        += g;               // diag element (i,i) at i*65
    o[(lane + 32) * 65] += g;
}

// ---------------------------------------------------------------------------
extern "C" void kernel_launch(void* const* d_in, const int* in_sizes, int n_in,
                              void* d_out, int out_size)
{
    const float* G      = (const float*)d_in[0];
    const float* coords = (const float*)d_in[1];
    const float* w1     = (const float*)d_in[2];
    const float* b1     = (const float*)d_in[3];
    const float* w2     = (const float*)d_in[4];
    const float* b2     = (const float*)d_in[5];
    const float* W      = (const float*)d_in[6];
    const float* b      = (const float*)d_in[7];
    float* out = (float*)d_out;

    k0_reset<<<1, 1>>>();
    k_fused<<<2048, 256>>>((const float4*)G, (float4*)out,
                           coords, w1, b1, w2, b2, W, b);
    k_fixup<<<BT_ / 8, 256>>>(out);
}

// round 11
// speedup vs baseline: 1.3820x; 1.3820x over previous
#include <cuda_runtime.h>
#include <math.h>

// Problem constants (fixed by reference)
#define B_   8
#define T_   4096
#define D_   64
#define R_   64
#define BT_  (B_ * T_)           // 32768 tokens
#define STRENGTH 0.1f
#define PHI_SCALE 0.17677669529663689f   // sqrt(2/64)
#define NPROD 1024                // producer blocks, 32 tokens each
#define PSPACE 3072               // producers live at bid%3==0 in [0, PSPACE)
#define NGRID (PSPACE + (BT_ - 2 * NPROD))   // 33792 blocks

// Scratch (static device globals — allocation-free)
__device__ float g_phi[BT_ * R_];          // 8 MB
__device__ float g_part[NPROD * R_];       // per-producer-block phi_sum partials
__device__ float g_phisum[B_ * R_];        // 2 KB
__device__ int   g_applied[BT_];           // 1 = diagonal fused in main kernel
__device__ unsigned g_count;               // producer completion counter
__device__ int g_flag;                     // phisum-ready flag

typedef unsigned long long u64;

// ---- f32x2 packed helpers (FFMA2 — only reachable via PTX) -----------------
__device__ __forceinline__ u64 pack2(float lo, float hi) {
    u64 v;
    asm("mov.b64 %0, {%1, %2};" : "=l"(v)
        : "r"(__float_as_uint(lo)), "r"(__float_as_uint(hi)));
    return v;
}
__device__ __forceinline__ u64 packdup(float x) {
    u64 v; unsigned u = __float_as_uint(x);
    asm("mov.b64 %0, {%1, %1};" : "=l"(v) : "r"(u));
    return v;
}
__device__ __forceinline__ void unpack2(u64 v, float& lo, float& hi) {
    unsigned a, b;
    asm("mov.b64 {%0, %1}, %2;" : "=r"(a), "=r"(b) : "l"(v));
    lo = __uint_as_float(a); hi = __uint_as_float(b);
}
__device__ __forceinline__ u64 ffma2(u64 a, u64 b, u64 c) {
    u64 d;
    asm("fma.rn.f32x2 %0, %1, %2, %3;" : "=l"(d) : "l"(a), "l"(b), "l"(c));
    return d;
}
__device__ __forceinline__ int ld_acquire(const int* p) {
    int v;
    asm volatile("ld.global.acquire.gpu.b32 %0, [%1];" : "=r"(v) : "l"(p) : "memory");
    return v;
}

// ---------------------------------------------------------------------------
// K0: reset counter/flag (graph replays reuse the globals)
// ---------------------------------------------------------------------------
__global__ void k0_reset() { g_count = 0; g_flag = 0; }

// ---------------------------------------------------------------------------
// Fused kernel, grid = 33792 x 256. Role by bid:
//   bid < 3072 && bid%3==0          -> producer (1024 total), 32 tokens each
//   otherwise                       -> copier, ONE 64x64 tile (R7-K4 shape)
// Producers never wait. Copiers check the flag once; unfused tiles are
// patched by k_fixup after the kernel boundary. No spins anywhere.
// ---------------------------------------------------------------------------
__global__ __launch_bounds__(256, 5)
void k_fused(const float4* __restrict__ G4, float4* __restrict__ out4,
             const float* __restrict__ coords,
             const float* __restrict__ w1, const float* __restrict__ b1,
             const float* __restrict__ w2, const float* __restrict__ b2,
             const float* __restrict__ W,  const float* __restrict__ b)
{
    __shared__ float2 Wsh2[D_ * 32];   // 16KB (producer only)
    __shared__ float2 Hsh2[D_ * 32];   // 16KB (producer only)
    __shared__ float  csh[8][4][D_];   // 8KB  (producer only)
    __shared__ float  psum[8][R_];     // 2KB  (producer only)
    __shared__ float  gsh;             // copier broadcast
    __shared__ int    ish;

    const int bid  = blockIdx.x;
    const int tid  = threadIdx.x;
    const int wid  = tid >> 5;
    const int lane = tid & 31;

    const bool isProd = (bid < PSPACE) && (bid % 3 == 0);

    if (isProd) {
        // ================= PRODUCER: phi + mass + phisum partial ===========
        const int kblk = bid / 3;           // 0..1023
        const int tokBase = kblk * 32;

        for (int i = tid; i < D_ * 32; i += 256) {
            const int d = i >> 5, l = i & 31;
            Wsh2[i] = make_float2(W[d * R_ + l], W[d * R_ + l + 32]);
            Hsh2[i] = make_float2(w1[l * D_ + d], w1[(l + 32) * D_ + d]);
        }
        {
            const float4* src = (const float4*)(coords + (size_t)tokBase * D_);
            float4* dstc = (float4*)&csh[0][0][0];
            #pragma unroll
            for (int g = 0; g < 2; ++g) dstc[tid + g * 256] = src[tid + g * 256];
        }
        const float bv_lo = b[lane],  bv_hi = b[lane + 32];
        const float b1_lo = b1[lane], b1_hi = b1[lane + 32];
        const float w2_lo = w2[lane], w2_hi = w2[lane + 32];
        const float b2v   = b2[0];
        __syncthreads();

        u64 accA[4], accH[4];
        {
            const u64 a0 = pack2(bv_lo, bv_hi);
            const u64 h0 = pack2(b1_lo, b1_hi);
            #pragma unroll
            for (int t = 0; t < 4; ++t) { accA[t] = a0; accH[t] = h0; }
        }

        #pragma unroll 1
        for (int dd = 0; dd < 16; ++dd) {
            float4 c4[4];
            #pragma unroll
            for (int t = 0; t < 4; ++t)
                c4[t] = *(const float4*)&csh[wid][t][dd * 4];   // broadcast
            #pragma unroll
            for (int k4 = 0; k4 < 4; ++k4) {
                const int d = dd * 4 + k4;
                const u64 wv = *(const u64*)&Wsh2[d * 32 + lane];
                const u64 hv = *(const u64*)&Hsh2[d * 32 + lane];
                #pragma unroll
                for (int t = 0; t < 4; ++t) {
                    const float c = (k4 == 0) ? c4[t].x : (k4 == 1) ? c4[t].y
                                  : (k4 == 2) ? c4[t].z : c4[t].w;
                    const u64 cc = packdup(c);
                    accA[t] = ffma2(cc, wv, accA[t]);
                    accH[t] = ffma2(cc, hv, accH[t]);
                }
            }
        }

        float ps_lo = 0.0f, ps_hi = 0.0f;
        const int gtok0 = tokBase + wid * 4;
        #pragma unroll 1
        for (int t = 0; t < 4; ++t) {
            float alo, ahi, hlo, hhi;
            unpack2(accA[t], alo, ahi);
            unpack2(accH[t], hlo, hhi);
            const float phi_lo = PHI_SCALE * cosf(alo);
            const float phi_hi = PHI_SCALE * cosf(ahi);
            const size_t po = (size_t)(gtok0 + t) * R_;
            g_phi[po + lane]      = phi_lo;
            g_phi[po + lane + 32] = phi_hi;

            float mp = fmaxf(hlo, 0.0f) * w2_lo + fmaxf(hhi, 0.0f) * w2_hi;
            #pragma unroll
            for (int off = 16; off > 0; off >>= 1)
                mp += __shfl_xor_sync(0xffffffffu, mp, off);
            const float x = mp + b2v;
            const float mass = fmaxf(x, 0.0f) + log1pf(expf(-fabsf(x)));
            ps_lo = fmaf(phi_lo, mass, ps_lo);
            ps_hi = fmaf(phi_hi, mass, ps_hi);
        }

        psum[wid][lane]      = ps_lo;
        psum[wid][lane + 32] = ps_hi;
        __syncthreads();
        if (tid < 64) {
            float s = 0.0f;
            #pragma unroll
            for (int w = 0; w < 8; ++w) s += psum[w][tid];
            g_part[kblk * R_ + tid] = s;
        }
        __syncthreads();
        __threadfence();                       // phi + partial visible device-wide
        if (tid == 0)
            ish = (atomicAdd(&g_count, 1u) == NPROD - 1u) ? 1 : 0;
        __syncthreads();

        if (ish) {
            __threadfence();                   // acquire side: see all partials
            // Last producer: reduce 128 chunk-partials per (batch, r), set flag
            for (int p = tid; p < B_ * R_; p += 256) {
                const int batch = p >> 6, r = p & 63;
                const float* base = g_part + (size_t)(batch * 128) * R_ + r;
                float s = 0.0f;
                #pragma unroll 8
                for (int c = 0; c < 128; ++c) s += base[(size_t)c * R_];
                g_phisum[p] = s;
            }
            __syncthreads();
            __threadfence();
            if (tid == 0) atomicExch(&g_flag, 1);   // release
        }
    } else {
        // ===== COPIER: one 64x64 tile, R7-K4 shape + one flag check ========
        const int cidx = (bid < PSPACE) ? ((bid / 3) * 2 + (bid % 3) - 1)
                                        : (2 * NPROD + (bid - PSPACE));
        const int tok = cidx;                    // 0..32767
        const float4* src = G4   + (size_t)tok * 1024;
        float4*       dst = out4 + (size_t)tok * 1024;

        float4 v[4];
        #pragma unroll
        for (int i = 0; i < 4; ++i)
            v[i] = __ldcs(&src[tid + i * 256]);  // batched streaming loads

        if (tid == 0) ish = ld_acquire(&g_flag);
        __syncthreads();
        const bool fused = (ish != 0);

        if (tid < 32) {
            float gv = 0.0f;
            if (fused) {
                const int batch = tok >> 12;
                const float* ph = g_phi    + (size_t)tok * R_;
                const float* ps = g_phisum + batch * R_;
                float s = ph[lane] * ps[lane] + ph[lane + 32] * ps[lane + 32];
                #pragma unroll
                for (int off = 16; off > 0; off >>= 1)
                    s += __shfl_down_sync(0xffffffffu, s, off);
                gv = STRENGTH * s;
            }
            if (lane == 0) { gsh = gv; g_applied[tok] = fused ? 1 : 0; }
        }
        __syncthreads();
        const float g = gsh;                     // 0.0f when not fused (exact)

        #pragma unroll
        for (int i = 0; i < 4; ++i) {
            const int idx = tid + i * 256;
            const int lin = idx << 2;
            float4 x = v[i];
            if (((lin    ) >> 6) == ((lin    ) & 63)) x.x += g;
            if (((lin + 1) >> 6) == ((lin + 1) & 63)) x.y += g;
            if (((lin + 2) >> 6) == ((lin + 2) & 63)) x.z += g;
            if (((lin + 3) >> 6) == ((lin + 3) & 63)) x.w += g;
            __stcs(&dst[idx], x);
        }
        // Block retires immediately — no waiting anywhere.
    }
}

// ---------------------------------------------------------------------------
// K-fixup: add 0.1*grav to the diagonal of tiles NOT fused in k_fused.
// Kernel boundary guarantees phisum/applied visibility. Warp per token.
// Bit-identical to the fused path (same single fp32 add on the same value).
// ---------------------------------------------------------------------------
__global__ __launch_bounds__(256)
void k_fixup(float* __restrict__ out)
{
    const int wid  = threadIdx.x >> 5;
    const int lane = threadIdx.x & 31;
    const int tok  = blockIdx.x * 8 + wid;

    if (g_applied[tok]) return;             // warp-uniform

    const int batch = tok >> 12;
    const float* ph = g_phi    + (size_t)tok * R_;
    const float* ps = g_phisum + batch * R_;
    float s = ph[lane] * ps[lane] + ph[lane + 32] * ps[lane + 32];
    #pragma unroll
    for (int off = 16; off > 0; off >>= 1)
        s += __shfl_xor_sync(0xffffffffu, s, off);
    const float g = STRENGTH * s;

    float* o = out + (size_t)tok * 4096;
    o[lane * 65]        += g;               // diag element (i,i) at i*65
    o[(lane + 32) * 65] += g;
}

// ---------------------------------------------------------------------------
extern "C" void kernel_launch(void* const* d_in, const int* in_sizes, int n_in,
                              void* d_out, int out_size)
{
    const float* G      = (const float*)d_in[0];
    const float* coords = (const float*)d_in[1];
    const float* w1     = (const float*)d_in[2];
    const float* b1     = (const float*)d_in[3];
    const float* w2     = (const float*)d_in[4];
    const float* b2     = (const float*)d_in[5];
    const float* W      = (const float*)d_in[6];
    const float* b      = (const float*)d_in[7];
    float* out = (float*)d_out;

    k0_reset<<<1, 1>>>();
    k_fused<<<NGRID, 256>>>((const float4*)G, (float4*)out,
                            coords, w1, b1, w2, b2, W, b);
    k_fixup<<<BT_ / 8, 256>>>(out);
}

// round 12
// speedup vs baseline: 1.6360x; 1.1838x over previous
#include <cuda_runtime.h>
#include <math.h>

// Problem constants (fixed by reference)
#define B_   8
#define T_   4096
#define D_   64
#define R_   64
#define BT_  (B_ * T_)           // 32768 tokens
#define STRENGTH 0.1f
#define PHI_SCALE 0.17677669529663689f   // sqrt(2/64)

// Scratch (static device globals — allocation-free)
__device__ float g_phi[BT_ * R_];          // 8 MB
__device__ float g_part[1024 * R_];        // per-block phi_sum partials
__device__ float g_phisum[B_ * R_];        // 2 KB

typedef unsigned long long u64;

// ---- f32x2 packed helpers (FFMA2 — only reachable via PTX) -----------------
__device__ __forceinline__ u64 pack2(float lo, float hi) {
    u64 v;
    asm("mov.b64 %0, {%1, %2};" : "=l"(v)
        : "r"(__float_as_uint(lo)), "r"(__float_as_uint(hi)));
    return v;
}
__device__ __forceinline__ u64 packdup(float x) {
    u64 v; unsigned u = __float_as_uint(x);
    asm("mov.b64 %0, {%1, %1};" : "=l"(v) : "r"(u));
    return v;
}
__device__ __forceinline__ void unpack2(u64 v, float& lo, float& hi) {
    unsigned a, b;
    asm("mov.b64 {%0, %1}, %2;" : "=r"(a), "=r"(b) : "l"(v));
    lo = __uint_as_float(a); hi = __uint_as_float(b);
}
__device__ __forceinline__ u64 ffma2(u64 a, u64 b, u64 c) {
    u64 d;
    asm("fma.rn.f32x2 %0, %1, %2, %3;" : "=l"(d) : "l"(a), "l"(b), "l"(c));
    return d;
}

// ---------------------------------------------------------------------------
// K1: phi + mass + per-block phi_sum partial.
// 1024 blocks x 256 threads (8 warps), warp = 4 tokens, thread = r-pair
// (lane, lane+32). Coords are stored PRE-DUPLICATED as u64 (c,c) in smem so
// the inner loop is pure {broadcast LDS + FFMA2} — no MOV-pair packing.
// ---------------------------------------------------------------------------
__global__ __launch_bounds__(256)
void k1_phi_mass(const float* __restrict__ coords,
                 const float* __restrict__ w1, const float* __restrict__ b1,
                 const float* __restrict__ w2, const float* __restrict__ b2,
                 const float* __restrict__ W,  const float* __restrict__ b)
{
    __shared__ float2 Wsh2[D_ * 32];            // 16KB: [d][lane]=(W[d][l],W[d][l+32])
    __shared__ float2 Hsh2[D_ * 32];            // 16KB: [d][lane]=(w1[l][d],w1[l+32][d])
    __shared__ __align__(16) u64 cdup[8][4][D_]; // 16KB: (c,c) per [warp][tok][d]
    __shared__ float  psum[8][R_];              // 2KB

    const int tid  = threadIdx.x;
    const int wid  = tid >> 5;         // 0..7
    const int lane = tid & 31;
    const int tokBase = blockIdx.x * 32;

    // Stage weights pre-paired for LDS.64 reads
    for (int i = tid; i < D_ * 32; i += 256) {
        const int d = i >> 5, l = i & 31;
        Wsh2[i] = make_float2(W[d * R_ + l], W[d * R_ + l + 32]);
        Hsh2[i] = make_float2(w1[l * D_ + d], w1[(l + 32) * D_ + d]);
    }
    // Stage 32 tokens' coords, duplicated into u64 lanes (coalesced gmem reads)
    {
        const float* src = coords + (size_t)tokBase * D_;
        u64* flat = &cdup[0][0][0];
        #pragma unroll
        for (int g = 0; g < 8; ++g) {
            const int i = tid + g * 256;            // i = tok32*64 + d
            flat[i] = packdup(src[i]);
        }
    }
    const float bv_lo = b[lane],  bv_hi = b[lane + 32];
    const float b1_lo = b1[lane], b1_hi = b1[lane + 32];
    const float w2_lo = w2[lane], w2_hi = w2[lane + 32];
    const float b2v   = b2[0];
    __syncthreads();

    u64 accA[4], accH[4];
    {
        const u64 a0 = pack2(bv_lo, bv_hi);
        const u64 h0 = pack2(b1_lo, b1_hi);
        #pragma unroll
        for (int t = 0; t < 4; ++t) { accA[t] = a0; accH[t] = h0; }
    }

    #pragma unroll 1
    for (int dd = 0; dd < 16; ++dd) {
        const int d0 = dd * 4;
        // 8 weight LDS.64 (lanes distinct, conflict-free)
        const u64 wv0 = *(const u64*)&Wsh2[(d0    ) * 32 + lane];
        const u64 wv1 = *(const u64*)&Wsh2[(d0 + 1) * 32 + lane];
        const u64 wv2 = *(const u64*)&Wsh2[(d0 + 2) * 32 + lane];
        const u64 wv3 = *(const u64*)&Wsh2[(d0 + 3) * 32 + lane];
        const u64 hv0 = *(const u64*)&Hsh2[(d0    ) * 32 + lane];
        const u64 hv1 = *(const u64*)&Hsh2[(d0 + 1) * 32 + lane];
        const u64 hv2 = *(const u64*)&Hsh2[(d0 + 2) * 32 + lane];
        const u64 hv3 = *(const u64*)&Hsh2[(d0 + 3) * 32 + lane];

        #pragma unroll
        for (int t = 0; t < 4; ++t) {
            // 2 broadcast LDS.128: 4 pre-duplicated coord u64s
            const ulonglong2 ca = *(const ulonglong2*)&cdup[wid][t][d0];
            const ulonglong2 cb = *(const ulonglong2*)&cdup[wid][t][d0 + 2];
            accA[t] = ffma2(ca.x, wv0, accA[t]);
            accH[t] = ffma2(ca.x, hv0, accH[t]);
            accA[t] = ffma2(ca.y, wv1, accA[t]);
            accH[t] = ffma2(ca.y, hv1, accH[t]);
            accA[t] = ffma2(cb.x, wv2, accA[t]);
            accH[t] = ffma2(cb.x, hv2, accH[t]);
            accA[t] = ffma2(cb.y, wv3, accA[t]);
            accH[t] = ffma2(cb.y, hv3, accH[t]);
        }
    }

    // Epilogue: phi (fast cos), mass (softplus), phi_sum partial
    float ps_lo = 0.0f, ps_hi = 0.0f;
    const int gtok0 = tokBase + wid * 4;
    #pragma unroll 1
    for (int t = 0; t < 4; ++t) {
        float alo, ahi, hlo, hhi;
        unpack2(accA[t], alo, ahi);
        unpack2(accH[t], hlo, hhi);
        const float phi_lo = PHI_SCALE * __cosf(alo);   // MUFU range reduction:
        const float phi_hi = PHI_SCALE * __cosf(ahi);   // ~1e-5 abs err @ |x|<100
        const size_t po = (size_t)(gtok0 + t) * R_;
        g_phi[po + lane]      = phi_lo;
        g_phi[po + lane + 32] = phi_hi;

        float mp = fmaxf(hlo, 0.0f) * w2_lo + fmaxf(hhi, 0.0f) * w2_hi;
        #pragma unroll
        for (int off = 16; off > 0; off >>= 1)
            mp += __shfl_xor_sync(0xffffffffu, mp, off);
        const float x = mp + b2v;
        const float mass = fmaxf(x, 0.0f) + log1pf(expf(-fabsf(x)));  // stable softplus
        ps_lo = fmaf(phi_lo, mass, ps_lo);
        ps_hi = fmaf(phi_hi, mass, ps_hi);
    }

    psum[wid][lane]      = ps_lo;
    psum[wid][lane + 32] = ps_hi;
    __syncthreads();
    if (tid < 64) {
        float s = 0.0f;
        #pragma unroll
        for (int w = 0; w < 8; ++w) s += psum[w][tid];
        g_part[blockIdx.x * R_ + tid] = s;
    }
}

// ---------------------------------------------------------------------------
// K2: reduce 128 block-partials per (batch, r) in fixed order. <<<8, 64>>>
// ---------------------------------------------------------------------------
__global__ void k2_reduce_phisum()
{
    const int batch = blockIdx.x;
    const int r = threadIdx.x;
    float s = 0.0f;
    #pragma unroll 8
    for (int c = 0; c < 128; ++c)
        s += g_part[(batch * 128 + c) * R_ + r];
    g_phisum[batch * R_ + r] = s;
}

// ---------------------------------------------------------------------------
// K4: grav (warp 0) + streaming copy of G with diagonal add.
// Block per token (32768 blocks), 256 threads — unchanged from R7 (86% DRAM).
// ---------------------------------------------------------------------------
__global__ __launch_bounds__(256)
void k4_copy(const float4* __restrict__ G4, float4* __restrict__ out4)
{
    const int tok = blockIdx.x;
    __shared__ float gsh;

    if (threadIdx.x < 32) {
        const int lane = threadIdx.x;
        const int batch = tok >> 12;                 // T = 4096
        const float* ph = g_phi    + (size_t)tok * R_;
        const float* ps = g_phisum + batch * R_;
        float s = ph[lane] * ps[lane] + ph[lane + 32] * ps[lane + 32];
        #pragma unroll
        for (int off = 16; off > 0; off >>= 1)
            s += __shfl_down_sync(0xffffffffu, s, off);
        if (lane == 0) gsh = STRENGTH * s;
    }
    __syncthreads();
    const float g = gsh;

    const float4* src = G4   + (size_t)tok * 1024;   // 4096 floats
    float4*       dst = out4 + (size_t)tok * 1024;

    float4 v[4];
    #pragma unroll
    for (int i = 0; i < 4; ++i)
        v[i] = __ldcs(&src[threadIdx.x + i * 256]);  // batched streaming loads

    #pragma unroll
    for (int i = 0; i < 4; ++i) {
        const int idx = threadIdx.x + i * 256;
        const int lin = idx << 2;
        float4 x = v[i];
        if (((lin    ) >> 6) == ((lin    ) & 63)) x.x += g;
        if (((lin + 1) >> 6) == ((lin + 1) & 63)) x.y += g;
        if (((lin + 2) >> 6) == ((lin + 2) & 63)) x.z += g;
        if (((lin + 3) >> 6) == ((lin + 3) & 63)) x.w += g;
        __stcs(&dst[idx], x);                        // streaming stores
    }
}

// ---------------------------------------------------------------------------
extern "C" void kernel_launch(void* const* d_in, const int* in_sizes, int n_in,
                              void* d_out, int out_size)
{
    const float* G      = (const float*)d_in[0];
    const float* coords = (const float*)d_in[1];
    const float* w1     = (const float*)d_in[2];
    const float* b1     = (const float*)d_in[3];
    const float* w2     = (const float*)d_in[4];
    const float* b2     = (const float*)d_in[5];
    const float* W      = (const float*)d_in[6];
    const float* b      = (const float*)d_in[7];
    float* out = (float*)d_out;

    k1_phi_mass<<<1024, 256>>>(coords, w1, b1, w2, b2, W, b);
    k2_reduce_phisum<<<8, 64>>>();
    k4_copy<<<BT_, 256>>>((const float4*)G, (float4*)out);
}